// round 11
// baseline (speedup 1.0000x reference)
#include <cuda_runtime.h>
#include <cuda_fp16.h>
#include <stdint.h>

// CINLayer via mma.sync (HMMA), z built in registers:
//   out_mat[c,(b,d)] = sum_k K2[c,k] * z[k,(b,d)],  z[k=(i,j),d] = x[b,i,d]*y[b,j,d]
// 16 warps = 4 c-quarters (m16) x 4 b-pairs (n64 = 2 b x 32 d). 8 b per CTA group.

#define BB 4096
#define IJ 1024
#define CC 64
#define DD 32
#define KROW 2064                 // padded K2 row stride (bytes), conflict-free ldmatrix
#define NT 512
#define BPG 8
#define NGROUP (BB / BPG)         // 512
#define NCTA 148
#define YTB (17 * 32 * 4)         // 2176 B per b: yT[d][a] half2 pairs, stride 17 words

#define OFF_K2 0
#define OFF_XD (CC * KROW)              // 132096
#define OFF_YT (OFF_XD + BPG * 4096)    // 164864
#define SMEM_BYTES (OFF_YT + BPG * YTB) // 182272

__device__ __forceinline__ uint32_t smem_u32(const void* p) {
    uint32_t a;
    asm("{ .reg .u64 t; cvta.to.shared.u64 t, %1; cvt.u32.u64 %0, t; }" : "=r"(a) : "l"(p));
    return a;
}
__device__ __forceinline__ unsigned hm2(unsigned a, unsigned b) {
    __half2 r = __hmul2(*(__half2*)&a, *(__half2*)&b);
    return *(unsigned*)&r;
}
__device__ __forceinline__ void ldmat4(unsigned& r0, unsigned& r1, unsigned& r2, unsigned& r3,
                                       uint32_t addr) {
    asm volatile("ldmatrix.sync.aligned.m8n8.x4.shared.b16 {%0,%1,%2,%3}, [%4];"
                 : "=r"(r0), "=r"(r1), "=r"(r2), "=r"(r3) : "r"(addr));
}
__device__ __forceinline__ void mma16816(float& c0, float& c1, float& c2, float& c3,
                                         unsigned a0, unsigned a1, unsigned a2, unsigned a3,
                                         unsigned b0, unsigned b1) {
    asm volatile("mma.sync.aligned.m16n8k16.row.col.f32.f16.f16.f32 "
                 "{%0,%1,%2,%3}, {%4,%5,%6,%7}, {%8,%9}, {%0,%1,%2,%3};"
                 : "+f"(c0), "+f"(c1), "+f"(c2), "+f"(c3)
                 : "r"(a0), "r"(a1), "r"(a2), "r"(a3), "r"(b0), "r"(b1));
}

__global__ __launch_bounds__(NT, 1)
void cin_hmma16_kernel(const float* __restrict__ x, const float* __restrict__ y,
                       const float* __restrict__ K, float* __restrict__ out_mat,
                       float* __restrict__ out_fin) {
    extern __shared__ char smem[];
    const int tid = threadIdx.x, lane = tid & 31, wid = tid >> 5;

    // ---- stage K2 once: f32 [64][1024] -> f16, rows padded to KROW bytes
    for (int p = tid; p < CC * IJ / 2; p += NT) {
        int row = p >> 9;
        int col = (2 * p) & (IJ - 1);
        float2 v = *(const float2*)(K + 2 * p);
        *(__half2*)(smem + OFF_K2 + row * KROW + col * 2) = __floats2half2_rn(v.x, v.y);
    }

    const int mq = wid & 3, pr = wid >> 2;      // c-quarter (16 rows), b-pair (0..3)
    const int q = lane & 3, gid = lane >> 2;
    const uint32_t aA0 = smem_u32(smem) + OFF_K2 +
                         (uint32_t)(mq * 16 + (lane & 15)) * KROW + (lane >> 4) * 16;

    for (int grp = blockIdx.x; grp < NGROUP; grp += gridDim.x) {
        const int base_b = grp * BPG;
        __syncthreads();            // previous group's reads done before restage

        // ---- stage 8 b's: xdup[i*32+d] = half2(x,x); yT[d*17+a] = half2(y[2a,d],y[2a+1,d])
        for (int p = tid; p < BPG * 256; p += NT) {          // 2048 float4 of x
            int lb = p >> 8, idx = p & 255;
            float4 v = ((const float4*)(x + (size_t)(base_b + lb) * IJ))[idx];
            uint4 u;
            { __half2 h = __half2half2(__float2half_rn(v.x)); u.x = *(unsigned*)&h; }
            { __half2 h = __half2half2(__float2half_rn(v.y)); u.y = *(unsigned*)&h; }
            { __half2 h = __half2half2(__float2half_rn(v.z)); u.z = *(unsigned*)&h; }
            { __half2 h = __half2half2(__float2half_rn(v.w)); u.w = *(unsigned*)&h; }
            ((uint4*)(smem + OFF_XD + lb * 4096))[idx] = u;
        }
        for (int p = tid; p < BPG * 512; p += NT) {          // 4096 yT entries
            int lb = p >> 9, r = p & 511;
            int d = r & 31, a = r >> 5;
            const float* yb = y + (size_t)(base_b + lb) * IJ;
            __half2 h = __floats2half2_rn(yb[(2 * a) * DD + d], yb[(2 * a + 1) * DD + d]);
            ((unsigned*)(smem + OFF_YT + lb * YTB))[d * 17 + a] = *(unsigned*)&h;
        }
        __syncthreads();

        // ---- per-warp: preload y pairs for its 2 b's (4 d-groups x 4 k-phases)
        const int lb0 = 2 * pr;
        unsigned ys[2][4][4];
#pragma unroll
        for (int bb = 0; bb < 2; bb++) {
            const unsigned* yT = (const unsigned*)(smem + OFF_YT + (lb0 + bb) * YTB);
#pragma unroll
            for (int g = 0; g < 4; g++)
#pragma unroll
                for (int s = 0; s < 4; s++)
                    ys[bb][g][s] = yT[(8 * g + gid) * 17 + q + 4 * s];
        }
        const unsigned* xd0 = (const unsigned*)(smem + OFF_XD + lb0 * 4096);
        const unsigned* xd1 = (const unsigned*)(smem + OFF_XD + (lb0 + 1) * 4096);

        float acc[8][4];
#pragma unroll
        for (int n = 0; n < 8; n++)
#pragma unroll
            for (int e = 0; e < 4; e++) acc[n][e] = 0.f;

        unsigned xd[2][4];
#pragma unroll 4
        for (int t = 0; t < 64; t++) {
            if (!(t & 1)) {
                const int i = t >> 1;
#pragma unroll
                for (int g = 0; g < 4; g++) {
                    xd[0][g] = xd0[i * 32 + 8 * g + gid];
                    xd[1][g] = xd1[i * 32 + 8 * g + gid];
                }
            }
            unsigned A[4];
            ldmat4(A[0], A[1], A[2], A[3], aA0 + t * 32);
            const int s0 = 2 * (t & 1);
#pragma unroll
            for (int bb = 0; bb < 2; bb++)
#pragma unroll
                for (int g = 0; g < 4; g++) {
                    unsigned bf0 = hm2(xd[bb][g], ys[bb][g][s0]);
                    unsigned bf1 = hm2(xd[bb][g], ys[bb][g][s0 + 1]);
                    const int n8 = bb * 4 + g;
                    mma16816(acc[n8][0], acc[n8][1], acc[n8][2], acc[n8][3],
                             A[0], A[1], A[2], A[3], bf0, bf1);
                }
        }

        // ---- epilogue
#pragma unroll
        for (int bb = 0; bb < 2; bb++) {
            const int b = base_b + lb0 + bb;
            float* om = out_mat + (size_t)b * CC * DD;
            const int c0 = mq * 16 + gid;
            float slo = 0.f, shi = 0.f;
#pragma unroll
            for (int g = 0; g < 4; g++) {
                const int n8 = bb * 4 + g;
                const int d0 = 8 * g + 2 * q;
                *(float2*)(om + c0 * DD + d0) = make_float2(acc[n8][0], acc[n8][1]);
                *(float2*)(om + (c0 + 8) * DD + d0) = make_float2(acc[n8][2], acc[n8][3]);
                slo += acc[n8][0] + acc[n8][1];
                shi += acc[n8][2] + acc[n8][3];
            }
            slo += __shfl_xor_sync(0xFFFFFFFFu, slo, 1);
            slo += __shfl_xor_sync(0xFFFFFFFFu, slo, 2);
            shi += __shfl_xor_sync(0xFFFFFFFFu, shi, 1);
            shi += __shfl_xor_sync(0xFFFFFFFFu, shi, 2);
            if (q == 0) {
                out_fin[(size_t)b * CC + c0] = slo;
                out_fin[(size_t)b * CC + c0 + 8] = shi;
            }
        }
    }
}

extern "C" void kernel_launch(void* const* d_in, const int* in_sizes, int n_in,
                              void* d_out, int out_size) {
    const float* x = (const float*)d_in[0];   // [B, 32, 32]
    const float* y = (const float*)d_in[1];   // [B, 32, 32]
    const float* K = (const float*)d_in[2];   // [64, 32, 32]
    float* out_mat = (float*)d_out;                          // [B, 64, 32]
    float* out_fin = (float*)d_out + (size_t)BB * CC * DD;   // [B, 64]

    static int done = 0;
    if (!done) {
        cudaFuncSetAttribute(cin_hmma16_kernel,
                             cudaFuncAttributeMaxDynamicSharedMemorySize, SMEM_BYTES);
        done = 1;
    }
    cin_hmma16_kernel<<<NCTA, NT, SMEM_BYTES>>>(x, y, K, out_mat, out_fin);
}

// round 14
// speedup vs baseline: 1.1003x; 1.1003x over previous
#include <cuda_runtime.h>
#include <cuda_fp16.h>
#include <stdint.h>

// CINLayer via mma.sync (HMMA), z built in registers, split-K:
//   out_mat[c,(b,d)] = sum_k K2[c,k] * z[k,(b,d)],  z[k=(i,j),d] = x[b,i,d]*y[b,j,d]
// 16 warps = 2 k-halves x (2 c-halves x 4 b-pairs). Warp tile m32 x n64 (2 b x 32 d).
// k-half-1 accs merged into k-half-0 via smem (reusing dead x/y staging region).

#define BB 4096
#define IJ 1024
#define CC 64
#define DD 32
#define KROW 2064                 // padded K2 row stride (bytes), conflict-free ldmatrix
#define NT 512
#define BPG 8
#define NGROUP (BB / BPG)         // 512
#define NCTA 148
#define YTB (17 * 32 * 4)         // 2176 B per b: yT[d][a] half2 pairs, stride 17 words

#define OFF_K2 0
#define OFF_XD (CC * KROW)              // 132096
#define OFF_YT (OFF_XD + BPG * 4096)    // 164864
#define OFF_MG OFF_XD                   // merge buffer reuses dead xd/yT (32 KB)
#define SMEM_BYTES (OFF_YT + BPG * YTB) // 182272

__device__ __forceinline__ uint32_t smem_u32(const void* p) {
    uint32_t a;
    asm("{ .reg .u64 t; cvta.to.shared.u64 t, %1; cvt.u32.u64 %0, t; }" : "=r"(a) : "l"(p));
    return a;
}
__device__ __forceinline__ unsigned hm2(unsigned a, unsigned b) {
    __half2 r = __hmul2(*(__half2*)&a, *(__half2*)&b);
    return *(unsigned*)&r;
}
__device__ __forceinline__ void ldmat4(unsigned& r0, unsigned& r1, unsigned& r2, unsigned& r3,
                                       uint32_t addr) {
    asm volatile("ldmatrix.sync.aligned.m8n8.x4.shared.b16 {%0,%1,%2,%3}, [%4];"
                 : "=r"(r0), "=r"(r1), "=r"(r2), "=r"(r3) : "r"(addr));
}
__device__ __forceinline__ void mma16816(float& c0, float& c1, float& c2, float& c3,
                                         unsigned a0, unsigned a1, unsigned a2, unsigned a3,
                                         unsigned b0, unsigned b1) {
    asm volatile("mma.sync.aligned.m16n8k16.row.col.f32.f16.f16.f32 "
                 "{%0,%1,%2,%3}, {%4,%5,%6,%7}, {%8,%9}, {%0,%1,%2,%3};"
                 : "+f"(c0), "+f"(c1), "+f"(c2), "+f"(c3)
                 : "r"(a0), "r"(a1), "r"(a2), "r"(a3), "r"(b0), "r"(b1));
}

__global__ __launch_bounds__(NT, 1)
void cin_splitk_kernel(const float* __restrict__ x, const float* __restrict__ y,
                       const float* __restrict__ K, float* __restrict__ out_mat,
                       float* __restrict__ out_fin) {
    extern __shared__ char smem[];
    const int tid = threadIdx.x, lane = tid & 31, wid = tid >> 5;

    // ---- stage K2 once: f32 [64][1024] -> f16, rows padded to KROW bytes
    for (int p = tid; p < CC * IJ / 2; p += NT) {
        int row = p >> 9;
        int col = (2 * p) & (IJ - 1);
        float2 v = *(const float2*)(K + 2 * p);
        *(__half2*)(smem + OFF_K2 + row * KROW + col * 2) = __floats2half2_rn(v.x, v.y);
    }

    const int kh = wid >> 3;                    // k-half: t in [32*kh, 32*kh+32)
    const int ws = wid & 7;
    const int mh = ws & 1, pr = ws >> 1;        // c-half, b-pair
    const int q = lane & 3, gid = lane >> 2;
    const uint32_t sb = smem_u32(smem);
    const uint32_t aA0 = sb + OFF_K2 +
                         (uint32_t)(mh * 32 + (lane & 15)) * KROW + (lane >> 4) * 16;

    for (int grp = blockIdx.x; grp < NGROUP; grp += gridDim.x) {
        const int base_b = grp * BPG;
        __syncthreads();            // prior group's reads (incl. merge) done

        // ---- stage 8 b's: xdup[i*32+d] = half2(x,x); yT[d*17+a] = half2(y[2a,d],y[2a+1,d])
        for (int p = tid; p < BPG * 256; p += NT) {          // 2048 float4 of x
            int lb = p >> 8, idx = p & 255;
            float4 v = ((const float4*)(x + (size_t)(base_b + lb) * IJ))[idx];
            uint4 u;
            { __half2 h = __half2half2(__float2half_rn(v.x)); u.x = *(unsigned*)&h; }
            { __half2 h = __half2half2(__float2half_rn(v.y)); u.y = *(unsigned*)&h; }
            { __half2 h = __half2half2(__float2half_rn(v.z)); u.z = *(unsigned*)&h; }
            { __half2 h = __half2half2(__float2half_rn(v.w)); u.w = *(unsigned*)&h; }
            ((uint4*)(smem + OFF_XD + lb * 4096))[idx] = u;
        }
        for (int p = tid; p < BPG * 512; p += NT) {          // 4096 yT entries
            int lb = p >> 9, r = p & 511;
            int d = r & 31, a = r >> 5;
            const float* yb = y + (size_t)(base_b + lb) * IJ;
            __half2 h = __floats2half2_rn(yb[(2 * a) * DD + d], yb[(2 * a + 1) * DD + d]);
            ((unsigned*)(smem + OFF_YT + lb * YTB))[d * 17 + a] = *(unsigned*)&h;
        }
        __syncthreads();

        // ---- per-warp: preload y pairs for its 2 b's (4 d-groups x 4 k-phases)
        const int lb0 = 2 * pr;
        unsigned ys[2][4][4];
#pragma unroll
        for (int bb = 0; bb < 2; bb++) {
            const unsigned* yT = (const unsigned*)(smem + OFF_YT + (lb0 + bb) * YTB);
#pragma unroll
            for (int g = 0; g < 4; g++)
#pragma unroll
                for (int s = 0; s < 4; s++)
                    ys[bb][g][s] = yT[(8 * g + gid) * 17 + q + 4 * s];
        }
        const unsigned* xd0 = (const unsigned*)(smem + OFF_XD + lb0 * 4096);
        const unsigned* xd1 = (const unsigned*)(smem + OFF_XD + (lb0 + 1) * 4096);

        float acc[2][8][4];
#pragma unroll
        for (int m = 0; m < 2; m++)
#pragma unroll
            for (int n = 0; n < 8; n++)
#pragma unroll
                for (int e = 0; e < 4; e++) acc[m][n][e] = 0.f;

        unsigned xd[2][4];
        const int t0 = 32 * kh;
#pragma unroll 4
        for (int tt = 0; tt < 32; tt++) {
            const int t = t0 + tt;
            if (!(tt & 1)) {
                const int i = t >> 1;
#pragma unroll
                for (int g = 0; g < 4; g++) {
                    xd[0][g] = xd0[i * 32 + 8 * g + gid];
                    xd[1][g] = xd1[i * 32 + 8 * g + gid];
                }
            }
            unsigned A0[4], A1[4];
            ldmat4(A0[0], A0[1], A0[2], A0[3], aA0 + t * 32);
            ldmat4(A1[0], A1[1], A1[2], A1[3], aA0 + 16 * KROW + t * 32);
            const int s0 = 2 * (tt & 1);
#pragma unroll
            for (int bb = 0; bb < 2; bb++)
#pragma unroll
                for (int g = 0; g < 4; g++) {
                    unsigned bf0 = hm2(xd[bb][g], ys[bb][g][s0]);
                    unsigned bf1 = hm2(xd[bb][g], ys[bb][g][s0 + 1]);
                    const int n8 = bb * 4 + g;
                    mma16816(acc[0][n8][0], acc[0][n8][1], acc[0][n8][2], acc[0][n8][3],
                             A0[0], A0[1], A0[2], A0[3], bf0, bf1);
                    mma16816(acc[1][n8][0], acc[1][n8][1], acc[1][n8][2], acc[1][n8][3],
                             A1[0], A1[1], A1[2], A1[3], bf0, bf1);
                }
        }

        // ---- split-K merge: kh=1 warps dump acc to smem (two 32KB waves), kh=0 adds
        __syncthreads();    // all MMA reads of xd/yT done; region reusable
#pragma unroll
        for (int wave = 0; wave < 2; wave++) {
            if (kh == 1 && (pr >> 1) == wave) {
                const int slot = (pr & 1) * 2 + mh;
                char* mg = smem + OFF_MG + slot * 8192 + lane * 16;
#pragma unroll
                for (int m = 0; m < 2; m++)
#pragma unroll
                    for (int n = 0; n < 8; n++)
                        *(float4*)(mg + (m * 8 + n) * 512) =
                            make_float4(acc[m][n][0], acc[m][n][1], acc[m][n][2], acc[m][n][3]);
            }
            __syncthreads();
            if (kh == 0 && (pr >> 1) == wave) {
                const int slot = (pr & 1) * 2 + mh;
                const char* mg = smem + OFF_MG + slot * 8192 + lane * 16;
#pragma unroll
                for (int m = 0; m < 2; m++)
#pragma unroll
                    for (int n = 0; n < 8; n++) {
                        float4 v = *(const float4*)(mg + (m * 8 + n) * 512);
                        acc[m][n][0] += v.x; acc[m][n][1] += v.y;
                        acc[m][n][2] += v.z; acc[m][n][3] += v.w;
                    }
            }
            if (wave == 0) __syncthreads();   // wave-0 reads done before wave-1 writes
        }

        // ---- epilogue (kh=0 warps only): out_mat + d-reduced out_fin
        if (kh == 0) {
#pragma unroll
            for (int bb = 0; bb < 2; bb++) {
                const int b = base_b + lb0 + bb;
                float* om = out_mat + (size_t)b * CC * DD;
#pragma unroll
                for (int m = 0; m < 2; m++) {
                    const int c0 = mh * 32 + m * 16 + gid;
                    float slo = 0.f, shi = 0.f;
#pragma unroll
                    for (int g = 0; g < 4; g++) {
                        const int n8 = bb * 4 + g;
                        const int d0 = 8 * g + 2 * q;
                        *(float2*)(om + c0 * DD + d0) =
                            make_float2(acc[m][n8][0], acc[m][n8][1]);
                        *(float2*)(om + (c0 + 8) * DD + d0) =
                            make_float2(acc[m][n8][2], acc[m][n8][3]);
                        slo += acc[m][n8][0] + acc[m][n8][1];
                        shi += acc[m][n8][2] + acc[m][n8][3];
                    }
                    slo += __shfl_xor_sync(0xFFFFFFFFu, slo, 1);
                    slo += __shfl_xor_sync(0xFFFFFFFFu, slo, 2);
                    shi += __shfl_xor_sync(0xFFFFFFFFu, shi, 1);
                    shi += __shfl_xor_sync(0xFFFFFFFFu, shi, 2);
                    if (q == 0) {
                        out_fin[(size_t)b * CC + c0] = slo;
                        out_fin[(size_t)b * CC + c0 + 8] = shi;
                    }
                }
            }
        }
    }
}

extern "C" void kernel_launch(void* const* d_in, const int* in_sizes, int n_in,
                              void* d_out, int out_size) {
    const float* x = (const float*)d_in[0];   // [B, 32, 32]
    const float* y = (const float*)d_in[1];   // [B, 32, 32]
    const float* K = (const float*)d_in[2];   // [64, 32, 32]
    float* out_mat = (float*)d_out;                          // [B, 64, 32]
    float* out_fin = (float*)d_out + (size_t)BB * CC * DD;   // [B, 64]

    static int done = 0;
    if (!done) {
        cudaFuncSetAttribute(cin_splitk_kernel,
                             cudaFuncAttributeMaxDynamicSharedMemorySize, SMEM_BYTES);
        done = 1;
    }
    cin_splitk_kernel<<<NCTA, NT, SMEM_BYTES>>>(x, y, K, out_mat, out_fin);
}